// round 16
// baseline (speedup 1.0000x reference)
#include <cuda_runtime.h>
#include <cstdint>
#include <math.h>

// ---------------------------------------------------------------------------
// ClassicalMappedQRNN fast path (alpha=beta=pi/2). B=8192 chains, S=4096.
// Warp-specialized + fused double-step + 2 WARPS PER SMSP.
//   block = 256 thr = 8 warps, grid = B/128 = 64 blocks:
//     wids {0,1,4,5} consumers  (SMSP 0,1 x2)
//     wids {2,3,6,7} producers  (SMSP 2,3 x2)
//   pair-group p = (wid&1)|((wid>>2)<<1); chain = blockIdx*128 + p*32 + lane.
// Producer streams ONE float4 PER STEP-PAIR: (C_t, S_t, C_{t+1}, S_{t+1}),
//   C = sqrt2*cos(phi/2) = sqrt(1+r), S = sqrt2*sin(phi/2) = x r/sqrt(1+r),
//   r = rsqrt(1+x^2).
// Consumer fused pair (R^2 = 2J, J(g)=(-g1,g0,g3,-g2); K = sqrt2/||G||):
//   cc = C C2 + S S2; P = C+S; M = C-S
//   a = g0-g1-g2+g3; b = g2+g3-g0-g1; d1 = C a + S b
//   m1 = 4 + K1 d1;  K2 = rsqrt(m1)
//   e = C2(g1+g2) + S2(g0-g3);  hf = cc - K1 e
//   m2 = 4 + 2K2 hf; K3 = rsqrt(m2)
//   G' = 2K2K1 J(G) + K2 (P,M,P,M) + (C2,-S2,S2,C2)
// ~31 fma-class/pair; 2 consumer warps per SMSP let HW interleaving fill
// the rsq/LDS stall slots -> fma-pipe-bound at ~31 cyc/step.
// ---------------------------------------------------------------------------

#define CHUNK  16
#define PAIRS  (CHUNK / 2)
#define TPB    256
#define GUARD4 4.000021f

__device__ __forceinline__ float rsqa(float x) {
    float y; asm("rsqrt.approx.f32 %0, %1;" : "=f"(y) : "f"(x)); return y;
}
__device__ __forceinline__ void barp(int id) {
    asm volatile("bar.sync %0, 64;" :: "r"(id) : "memory");
}

// [pairgrp(4)][buf(2)][tp(8)][lane(32)] float4 = 32768 bytes (static)
__shared__ float4 sb4[4 * 2 * PAIRS * 32];

// ---------------- consumer side ----------------
struct SState { float g0, g1, g2, g3, K; };

__device__ __forceinline__ void s_init(SState& s, float C, float S) {
    s.g0 = C; s.g1 = -S; s.g2 = S; s.g3 = C;           // G0 = v0
    s.K  = 0.70710678118654752f;                        // sqrt2/||G0||
}

__device__ __forceinline__ void s_direct(SState& s, float C, float S) {
    float w0 = s.g0 - s.g1, w1 = s.g0 + s.g1;
    float w2 = s.g2 + s.g3, w3 = s.g3 - s.g2;
    float d  = fmaf(S, w2 - w1, C * (w0 + w3));
    float m  = fmaf(s.K, d, GUARD4);
    float Kn = rsqa(m);
    float n0 = fmaf(s.K, w0,  C);
    float n1 = fmaf(s.K, w1, -S);
    float n2 = fmaf(s.K, w2,  S);
    float n3 = fmaf(s.K, w3,  C);
    s.g0 = n0; s.g1 = n1; s.g2 = n2; s.g3 = n3; s.K = Kn;
}

// fused pair: q = (C_t, S_t, C_{t+1}, S_{t+1})
__device__ __forceinline__ void s_pair(SState& s, float4 q) {
    float C = q.x, Sx = q.y, C2 = q.z, S2 = q.w;
    float cc = fmaf(Sx, S2, C * C2);
    float P  = C + Sx;
    float M  = C - Sx;
    // d1 from state butterflies
    float w01 = s.g0 - s.g1, w23 = s.g2 - s.g3;
    float p01 = s.g0 + s.g1, p23 = s.g2 + s.g3;
    float a = w01 - w23;
    float b = p23 - p01;
    float d1 = fmaf(Sx, b, C * a);
    float m1 = fmaf(s.K, d1, GUARD4);
    float K2 = rsqa(m1);                              // chain
    // d2 path
    float gam = s.g1 + s.g2;
    float bet = s.g0 - s.g3;
    float e   = fmaf(S2, bet, C2 * gam);
    float hf  = fmaf(-s.K, e, cc);
    float K22 = K2 + K2;
    float m2  = fmaf(K22, hf, GUARD4);
    float K3  = rsqa(m2);                             // chain
    // fused state update
    float KK2 = K22 * s.K;                            // 2 K2 K1
    float KP  = K2 * P;
    float KM  = K2 * M;
    float n0 = fmaf(-KK2, s.g1, KP + C2);
    float n2 = fmaf( KK2, s.g3, KP + S2);
    float n1 = fmaf( KK2, s.g0, KM - S2);
    float n3 = fmaf(-KK2, s.g2, KM + C2);
    s.g0 = n0; s.g1 = n1; s.g2 = n2; s.g3 = n3; s.K = K3;
}

__device__ __forceinline__ void s_renorm(SState& s) {
    float ss = (s.g0 * s.g0 + s.g1 * s.g1) + (s.g2 * s.g2 + s.g3 * s.g3);
    s.K = rsqa(0.5f * ss);                            // exact sqrt2/||G||
}

template <bool FIRST>
__device__ __forceinline__ void consume_chunk(SState& s, const float4* sb) {
    if (FIRST) {
        float4 q0 = sb[0];
        s_init(s, q0.x, q0.y);
        s_direct(s, q0.z, q0.w);
        #pragma unroll
        for (int tp = 1; tp < PAIRS; tp++) s_pair(s, sb[tp * 32]);
    } else {
        #pragma unroll
        for (int tp = 0; tp < PAIRS; tp++) s_pair(s, sb[tp * 32]);
    }
    s_renorm(s);   // exact rescale every 16 steps: kills approx-rsqrt drift
}

// ---------------- producer side ----------------
struct PReg { float4 a[CHUNK / 4]; };

__device__ __forceinline__ void p_load(PReg& r, const float* __restrict__ xrow,
                                       int c) {
    const float4* p = reinterpret_cast<const float4*>(xrow + c * CHUNK);
    #pragma unroll
    for (int i = 0; i < CHUNK / 4; i++) r.a[i] = __ldg(p + i);
}

__device__ __forceinline__ void p_trig(float x, float& C, float& S) {
    float tq = fmaf(x, x, 1.0f);
    float r  = rsqa(tq);
    float e  = r + 1.0f;
    float q  = rsqa(e);
    C = e * q;                             // sqrt2 cos(phi/2)
    S = (x * r) * q;                       // sqrt2 sin(phi/2)
}

__device__ __forceinline__ void p_chunk(const PReg& r, float4* wb) {
    #pragma unroll
    for (int i = 0; i < CHUNK / 4; i++) {
        float C0, S0, C1, S1;
        p_trig(r.a[i].x, C0, S0);
        p_trig(r.a[i].y, C1, S1);
        wb[(i * 2 + 0) * 32] = make_float4(C0, S0, C1, S1);
        p_trig(r.a[i].z, C0, S0);
        p_trig(r.a[i].w, C1, S1);
        wb[(i * 2 + 1) * 32] = make_float4(C0, S0, C1, S1);
    }
}

// ---------------- fallback ----------------
__device__ void run_simple(const float* __restrict__ xrow, float* __restrict__ outb,
                           int S, float ca, float sa, float cb, float sb) {
    float h0 = 0.f, h1 = 0.f, h2 = 0.f, h3 = 0.f;
    for (int t = 0; t < S; t++) {
        float xv = xrow[t];
        float phi = atanf(xv);
        float c = cosf(0.5f * phi);
        float s = sinf(0.5f * phi);
        float u0 = ca * c + cb * h0 - sb * h1;
        float u1 = -(sa * s) + sb * h0 + cb * h1;
        float u2 = ca * s + cb * h2 + sb * h3;
        float u3 = sa * c - sb * h2 + cb * h3;
        float ss = u0*u0 + u1*u1 + u2*u2 + u3*u3;
        float rn = rsqrtf(ss);
        h0 = u0 * rn; h1 = u1 * rn; h2 = u2 * rn; h3 = u3 * rn;
    }
    *outb = (h0*h0 + h1*h1) - (h2*h2 + h3*h3);
}

// ---------------- kernel ----------------
__global__ void __launch_bounds__(TPB, 1)
qrnn_kernel(const float* __restrict__ x, const float* __restrict__ pa,
            const float* __restrict__ pb, float* __restrict__ out, int B, int S) {
    int tid  = threadIdx.x;
    int wid  = tid >> 5;
    int lane = tid & 31;

    float alpha = __ldg(pa);
    float beta  = __ldg(pb);
    const float PIO2 = 1.57079632679489662f;
    bool fast = (fabsf(alpha - PIO2) < 1e-5f) && (fabsf(beta - PIO2) < 1e-5f)
                && (S % 32 == 0) && (S >= 128) && (B % 128 == 0);

    if (!fast) {
        int b = blockIdx.x * TPB + tid;
        if (b < B) {
            float ca = cosf(0.5f * alpha), sa = sinf(0.5f * alpha);
            float cb = cosf(0.5f * beta),  sb = sinf(0.5f * beta);
            run_simple(x + (size_t)b * S, out + b, S, ca, sa, cb, sb);
        }
        return;
    }

    const int nch = S / CHUNK;                 // even (S % 32 == 0)
    int p  = (wid & 1) | ((wid >> 2) << 1);    // pair-group 0..3
    int b  = blockIdx.x * 128 + p * 32 + lane; // this role's chain
    int id = 1 + p;                            // named barrier per pair-group
    bool consumer = ((wid >> 1) & 1) == 0;     // wids {0,1,4,5}

    if (consumer) {
        const float4* rb0 = sb4 + (p * 2 + 0) * (PAIRS * 32) + lane;
        const float4* rb1 = sb4 + (p * 2 + 1) * (PAIRS * 32) + lane;

        SState s;
        barp(id);                                  // wait: chunk 0 ready
        #pragma unroll 1
        for (int c = 0; c < nch; c++) {
            if (c == 0) consume_chunk<true >(s, rb0);
            else        consume_chunk<false>(s, (c & 1) ? rb1 : rb0);
            barp(id);
        }

        float a01 = s.g0 * s.g0 + s.g1 * s.g1;
        float a23 = s.g2 * s.g2 + s.g3 * s.g3;
        out[b] = (a01 - a23) / (a01 + a23);
    } else {
        const float* xrow = x + (size_t)b * S;
        float4* wb0 = sb4 + (p * 2 + 0) * (PAIRS * 32) + lane;
        float4* wb1 = sb4 + (p * 2 + 1) * (PAIRS * 32) + lane;

        PReg ra, rbuf;
        p_load(ra, xrow, 0);

        #pragma unroll 1
        for (int c = 0; c < nch; c += 2) {
            int c1 = (c + 1 < nch) ? c + 1 : c;
            p_load(rbuf, xrow, c1);
            p_chunk(ra, wb0);                      // chunk c   -> buf 0
            barp(id);
            int c2 = (c + 2 < nch) ? c + 2 : c1;
            p_load(ra, xrow, c2);
            p_chunk(rbuf, wb1);                    // chunk c+1 -> buf 1
            barp(id);
        }
        barp(id);                                  // match consumer's final wait
    }
}

extern "C" void kernel_launch(void* const* d_in, const int* in_sizes, int n_in,
                              void* d_out, int out_size) {
    const float* x  = (const float*)d_in[0];
    const float* pa = (const float*)d_in[1];
    const float* pb = (const float*)d_in[2];
    float* out = (float*)d_out;

    int B = out_size;                 // 8192
    int S = in_sizes[0] / B;          // 4096

    int grid = (B + 127) / 128;       // 64 blocks x 256 threads
    qrnn_kernel<<<grid, TPB>>>(x, pa, pb, out, B, S);
}